// round 3
// baseline (speedup 1.0000x reference)
#include <cuda_runtime.h>
#include <cuda_bf16.h>
#include <stdint.h>

// Embedding gather: out[row, :] = table[ids[row], :]
// ids: int32 OR int64 [16384] (dtype auto-detected at runtime),
// table: fp32 [vocab, 768], out: fp32 [n_rows, 768].
// One CTA per token row; 192 threads each move one float4 (768 fp32 = 192*4).
// Pure HBM-bound copy: ~96 MiB total traffic.

#define D_MODEL 768
#define VEC_PER_ROW (D_MODEL / 4)   // 192 float4 per row

// 0 = ids are int32, 1 = ids are int64. Set by probe kernel (deterministic,
// depends only on input contents -> graph-replay safe).
__device__ int g_ids_is64;

__global__ void probe_ids_dtype_kernel(const void* __restrict__ ids_raw,
                                       int n_rows, long long vocab)
{
    if (threadIdx.x != 0 || blockIdx.x != 0) return;
    // If the data is really int32, reading it as int64 pairs two tokens:
    // value = lo + hi*2^32 with hi almost surely nonzero somewhere in the
    // first 16 entries -> out of [0, vocab) range.
    const long long* as64 = (const long long*)ids_raw;
    int n_check = n_rows < 16 ? n_rows : 16;
    int ok64 = 1;
    for (int i = 0; i < n_check; i++) {
        long long v = as64[i];
        if (v < 0 || v >= vocab) { ok64 = 0; break; }
    }
    g_ids_is64 = ok64;
}

__global__ __launch_bounds__(VEC_PER_ROW) void embedding_gather_kernel(
    const void* __restrict__ ids_raw,
    const float4* __restrict__ table,
    float4* __restrict__ out,
    int n_rows, long long vocab)
{
    int row = blockIdx.x;
    if (row >= n_rows) return;

    // Broadcast loads: flag + id (one L1 sector each per CTA).
    long long tok;
    if (g_ids_is64) {
        tok = __ldg(((const long long*)ids_raw) + row);
    } else {
        tok = (long long)__ldg(((const int*)ids_raw) + row);
    }
    // Safety clamp: guarantees no fault even under misdetection, so a wrong
    // guess still yields a profiled (failing) run instead of an IMA abort.
    tok = tok < 0 ? 0 : (tok >= vocab ? vocab - 1 : tok);

    const float4* __restrict__ src = table + (size_t)tok * VEC_PER_ROW;
    float4* __restrict__ dst = out + (size_t)row * VEC_PER_ROW;

    dst[threadIdx.x] = __ldg(src + threadIdx.x);
}

extern "C" void kernel_launch(void* const* d_in, const int* in_sizes, int n_in,
                              void* d_out, int out_size)
{
    // Identify inputs by element count: ids is the small array, table the big one.
    int ids_idx = 0, tab_idx = 1;
    if (n_in >= 2 && in_sizes[0] > in_sizes[1]) { ids_idx = 1; tab_idx = 0; }

    const void*   ids = d_in[ids_idx];
    const float4* tab = (const float4*)d_in[tab_idx];
    float4*       out = (float4*)d_out;

    int n_rows = out_size / D_MODEL;                           // 16384
    long long vocab = (long long)in_sizes[tab_idx] / D_MODEL;  // 50257

    probe_ids_dtype_kernel<<<1, 32>>>(ids, n_rows, vocab);
    embedding_gather_kernel<<<n_rows, VEC_PER_ROW>>>(ids, tab, out, n_rows, vocab);
}

// round 6
// speedup vs baseline: 1.2476x; 1.2476x over previous
#include <cuda_runtime.h>
#include <cuda_bf16.h>
#include <stdint.h>

// Embedding gather: out[row, :] = table[ids[row], :]
// ids: int32 OR int64 (dtype auto-detected), table: fp32 [vocab, 768],
// out: fp32 [n_rows, 768].
// R=8 rows per CTA, 192 threads; each thread front-batches 8 independent
// float4 loads (MLP=8) then 8 stores. Latency-hiding version of R3 kernel.

#define D_MODEL 768
#define VEC_PER_ROW (D_MODEL / 4)   // 192 float4 per row
#define ROWS_PER_CTA 8

// 0 = ids are int32, 1 = ids are int64. Set by probe kernel (deterministic,
// depends only on input contents -> graph-replay safe).
__device__ int g_ids_is64;

__global__ void probe_ids_dtype_kernel(const void* __restrict__ ids_raw,
                                       int n_rows, long long vocab)
{
    if (threadIdx.x != 0 || blockIdx.x != 0) return;
    // int32 data read as int64 pairs two tokens -> value >= 2^32 almost surely
    // somewhere in the first 16 entries -> out of [0, vocab).
    const long long* as64 = (const long long*)ids_raw;
    int n_check = n_rows < 16 ? n_rows : 16;
    int ok64 = 1;
    for (int i = 0; i < n_check; i++) {
        long long v = as64[i];
        if (v < 0 || v >= vocab) { ok64 = 0; break; }
    }
    g_ids_is64 = ok64;
}

__global__ __launch_bounds__(VEC_PER_ROW) void embedding_gather_kernel(
    const void* __restrict__ ids_raw,
    const float4* __restrict__ table,
    float4* __restrict__ out,
    int n_rows, long long vocab)
{
    __shared__ size_t s_off[ROWS_PER_CTA];   // row offsets into table (float4 units)

    int base = blockIdx.x * ROWS_PER_CTA;

    if (threadIdx.x < ROWS_PER_CTA) {
        int r = base + threadIdx.x;
        long long tok = 0;
        if (r < n_rows) {
            if (g_ids_is64) tok = __ldg(((const long long*)ids_raw) + r);
            else            tok = (long long)__ldg(((const int*)ids_raw) + r);
            // Safety clamp: no fault even under dtype misdetection.
            tok = tok < 0 ? 0 : (tok >= vocab ? vocab - 1 : tok);
        }
        s_off[threadIdx.x] = (size_t)tok * VEC_PER_ROW;
    }
    __syncthreads();

    int i = threadIdx.x;
    float4* __restrict__ dst = out + (size_t)base * VEC_PER_ROW + i;

    // Front-batch 8 independent 16B loads -> MLP=8 per thread.
    float4 v[ROWS_PER_CTA];
#pragma unroll
    for (int j = 0; j < ROWS_PER_CTA; j++) {
        v[j] = __ldg(table + s_off[j] + i);
    }

#pragma unroll
    for (int j = 0; j < ROWS_PER_CTA; j++) {
        if (base + j < n_rows) dst[(size_t)j * VEC_PER_ROW] = v[j];
    }
}

extern "C" void kernel_launch(void* const* d_in, const int* in_sizes, int n_in,
                              void* d_out, int out_size)
{
    // Identify inputs by element count: ids is the small array, table the big one.
    int ids_idx = 0, tab_idx = 1;
    if (n_in >= 2 && in_sizes[0] > in_sizes[1]) { ids_idx = 1; tab_idx = 0; }

    const void*   ids = d_in[ids_idx];
    const float4* tab = (const float4*)d_in[tab_idx];
    float4*       out = (float4*)d_out;

    int n_rows = out_size / D_MODEL;                           // 16384
    long long vocab = (long long)in_sizes[tab_idx] / D_MODEL;  // 50257

    int n_blocks = (n_rows + ROWS_PER_CTA - 1) / ROWS_PER_CTA; // 2048

    probe_ids_dtype_kernel<<<1, 32>>>(ids, n_rows, vocab);
    embedding_gather_kernel<<<n_blocks, VEC_PER_ROW>>>(ids, tab, out, n_rows, vocab);
}